// round 1
// baseline (speedup 1.0000x reference)
#include <cuda_runtime.h>
#include <math.h>

// Problem constants (fixed by the dataset)
constexpr int N_NODES = 100000;
constexpr int N_HEDGE = 25000;
constexpr int N_EDGES = 600000;
constexpr int D       = 128;      // feature dim (in = hid = out = 128)

// ---------------------------------------------------------------------------
// Scratch (static __device__ arrays: no allocation allowed in kernel_launch)
// ---------------------------------------------------------------------------
__device__ float g_m   [N_HEDGE * D];   // hyperedge accumulator (H^T x)
__device__ float g_m2  [N_HEDGE * D];   // (B^-1 m) @ W
__device__ float g_acc [N_NODES * D];   // node accumulator
__device__ float g_xbuf[N_NODES * D];   // inter-layer node features
__device__ float g_dinv[N_NODES];
__device__ float g_binv[N_HEDGE];
__device__ int   g_degn[N_NODES];
__device__ int   g_dege[N_HEDGE];

// ---------------------------------------------------------------------------
// Degree computation
// ---------------------------------------------------------------------------
__global__ void zero_deg_kernel() {
    int i = blockIdx.x * blockDim.x + threadIdx.x;
    if (i < N_NODES) g_degn[i] = 0;
    if (i < N_HEDGE) g_dege[i] = 0;
}

__global__ void count_deg_kernel(const int* __restrict__ node_idx,
                                 const int* __restrict__ hedge_idx) {
    int i = blockIdx.x * blockDim.x + threadIdx.x;
    if (i < N_EDGES) {
        atomicAdd(&g_degn[node_idx[i]], 1);
        atomicAdd(&g_dege[hedge_idx[i]], 1);
    }
}

__global__ void invert_deg_kernel() {
    int i = blockIdx.x * blockDim.x + threadIdx.x;
    if (i < N_NODES) {
        int d = g_degn[i];
        g_dinv[i] = d > 0 ? 1.0f / (float)d : 0.0f;
    }
    if (i < N_HEDGE) {
        int d = g_dege[i];
        g_binv[i] = d > 0 ? 1.0f / (float)d : 0.0f;
    }
}

// ---------------------------------------------------------------------------
// Zero fill (float4)
// ---------------------------------------------------------------------------
__global__ void zero_f4_kernel(float4* __restrict__ p, int n4) {
    int i = blockIdx.x * blockDim.x + threadIdx.x;
    if (i < n4) p[i] = make_float4(0.f, 0.f, 0.f, 0.f);
}

// ---------------------------------------------------------------------------
// Warp-per-edge gather + vector reduction scatter.
// Each warp handles one incidence: reads a full 128-float row (32 x float4,
// 512B fully coalesced) from src[src_idx[e]] and red.add.v4 into
// dst[dst_idx[e]]. Both tables are L2-resident.
// ---------------------------------------------------------------------------
__global__ void __launch_bounds__(256)
scatter_kernel(const float* __restrict__ src, float* __restrict__ dst,
               const int* __restrict__ src_idx, const int* __restrict__ dst_idx,
               int n_edges) {
    int gw   = (blockIdx.x * blockDim.x + threadIdx.x) >> 5;
    int lane = threadIdx.x & 31;
    if (gw >= n_edges) return;
    int s = src_idx[gw];
    int d = dst_idx[gw];
    float4 v = ((const float4*)(src + (size_t)s * D))[lane];
    float4* p = ((float4*)(dst + (size_t)d * D)) + lane;
    asm volatile("red.global.add.v4.f32 [%0], {%1,%2,%3,%4};"
                 :: "l"(p), "f"(v.x), "f"(v.y), "f"(v.z), "f"(v.w)
                 : "memory");
}

// ---------------------------------------------------------------------------
// GEMM at the hyperedge level: C[r,:] = (rscale[r] * A[r,:]) @ W
// W (128x128 fp32 = 64KB) fully resident in dynamic smem.
// Block tile: 32 rows x 128 cols, 256 threads, each thread = 4 rows x float4.
// ---------------------------------------------------------------------------
__global__ void __launch_bounds__(256)
gemm_scaled_kernel(const float* __restrict__ A, const float* __restrict__ rscale,
                   const float* __restrict__ W, float* __restrict__ C, int nrows) {
    extern __shared__ float sm[];
    float* Ws = sm;              // 128*128
    float* Xs = sm + 128 * 128;  // 32*128
    int t = threadIdx.x;

    // Load full W into smem (coalesced float4)
    for (int i = t; i < 128 * 128 / 4; i += 256)
        ((float4*)Ws)[i] = ((const float4*)W)[i];

    int row0 = blockIdx.x * 32;
    // Load X tile, scaled by per-row rscale; zero-pad past nrows
    for (int i = t; i < 32 * 128 / 4; i += 256) {
        int r  = i >> 5;        // 0..31
        int c4 = i & 31;
        int gr = row0 + r;
        float4 v = make_float4(0.f, 0.f, 0.f, 0.f);
        if (gr < nrows) {
            v = ((const float4*)(A + (size_t)gr * D))[c4];
            float s = rscale[gr];
            v.x *= s; v.y *= s; v.z *= s; v.w *= s;
        }
        ((float4*)Xs)[i] = v;
    }
    __syncthreads();

    int tx = t & 31;   // column group: cols [4*tx, 4*tx+3]
    int ty = t >> 5;   // row group: rows ty, ty+8, ty+16, ty+24

    float4 acc[4];
    #pragma unroll
    for (int r = 0; r < 4; r++) acc[r] = make_float4(0.f, 0.f, 0.f, 0.f);

    #pragma unroll 8
    for (int k = 0; k < 128; k++) {
        float4 wv = ((const float4*)(Ws + k * 128))[tx];
        #pragma unroll
        for (int r = 0; r < 4; r++) {
            float a = Xs[(ty + r * 8) * 128 + k];
            acc[r].x = fmaf(a, wv.x, acc[r].x);
            acc[r].y = fmaf(a, wv.y, acc[r].y);
            acc[r].z = fmaf(a, wv.z, acc[r].z);
            acc[r].w = fmaf(a, wv.w, acc[r].w);
        }
    }

    #pragma unroll
    for (int r = 0; r < 4; r++) {
        int gr = row0 + ty + r * 8;
        if (gr < nrows)
            ((float4*)(C + (size_t)gr * D))[tx] = acc[r];
    }
}

// ---------------------------------------------------------------------------
// Finalize: out[n][c] = ELU(acc[n][c] * dinv[n] + bias[c])
// ---------------------------------------------------------------------------
__device__ __forceinline__ float elu_f(float x) {
    return x > 0.0f ? x : expm1f(x);
}

__global__ void __launch_bounds__(256)
finalize_kernel(const float* __restrict__ acc, const float* __restrict__ dinv,
                const float* __restrict__ bias, float* __restrict__ out, int n) {
    int i = blockIdx.x * blockDim.x + threadIdx.x;   // over n*32 float4s
    if (i >= n * 32) return;
    int row = i >> 5;
    int c4  = i & 31;
    float s  = dinv[row];
    float4 v = ((const float4*)acc)[i];
    float4 b = ((const float4*)bias)[c4];
    v.x = elu_f(fmaf(v.x, s, b.x));
    v.y = elu_f(fmaf(v.y, s, b.y));
    v.z = elu_f(fmaf(v.z, s, b.z));
    v.w = elu_f(fmaf(v.w, s, b.w));
    ((float4*)out)[i] = v;
}

// ---------------------------------------------------------------------------
// Launch
// ---------------------------------------------------------------------------
static void run_layer(const float* x_in, const float* W, const float* b, float* x_out,
                      const int* node_idx, const int* hedge_idx,
                      float* p_m, float* p_m2, float* p_acc,
                      const float* p_binv, const float* p_dinv) {
    const int ZB_M   = (N_HEDGE * D / 4 + 255) / 256;
    const int ZB_N   = (N_NODES * D / 4 + 255) / 256;
    const int SCB    = (N_EDGES * 32 + 255) / 256;
    const int GEMB   = (N_HEDGE + 31) / 32;
    const int FINB   = (N_NODES * 32 + 255) / 256;
    const int GEMM_SMEM = (128 * 128 + 32 * 128) * (int)sizeof(float);

    // node -> hyperedge: m[h] += x[node[e]]
    zero_f4_kernel<<<ZB_M, 256>>>((float4*)p_m, N_HEDGE * D / 4);
    scatter_kernel<<<SCB, 256>>>(x_in, p_m, node_idx, hedge_idx, N_EDGES);
    // m2 = (B^-1 m) @ W   (GEMM at hyperedge level: 4x fewer FLOPs)
    gemm_scaled_kernel<<<GEMB, 256, GEMM_SMEM>>>(p_m, p_binv, W, p_m2, N_HEDGE);
    // hyperedge -> node: acc[n] += m2[hedge[e]]
    zero_f4_kernel<<<ZB_N, 256>>>((float4*)p_acc, N_NODES * D / 4);
    scatter_kernel<<<SCB, 256>>>(p_m2, p_acc, hedge_idx, node_idx, N_EDGES);
    // out = ELU(acc * D^-1 + b)
    finalize_kernel<<<FINB, 256>>>(p_acc, p_dinv, b, x_out, N_NODES);
}

extern "C" void kernel_launch(void* const* d_in, const int* in_sizes, int n_in,
                              void* d_out, int out_size) {
    const float* x  = (const float*)d_in[0];
    const float* W1 = (const float*)d_in[1];
    const float* b1 = (const float*)d_in[2];
    const float* W2 = (const float*)d_in[3];
    const float* b2 = (const float*)d_in[4];
    const float* W3 = (const float*)d_in[5];
    const float* b3 = (const float*)d_in[6];
    const int* node_idx  = (const int*)d_in[7];
    const int* hedge_idx = (const int*)d_in[8];
    float* out = (float*)d_out;

    float *p_m, *p_m2, *p_acc, *p_xbuf, *p_binv, *p_dinv;
    cudaGetSymbolAddress((void**)&p_m,    g_m);
    cudaGetSymbolAddress((void**)&p_m2,   g_m2);
    cudaGetSymbolAddress((void**)&p_acc,  g_acc);
    cudaGetSymbolAddress((void**)&p_xbuf, g_xbuf);
    cudaGetSymbolAddress((void**)&p_binv, g_binv);
    cudaGetSymbolAddress((void**)&p_dinv, g_dinv);

    cudaFuncSetAttribute(gemm_scaled_kernel,
                         cudaFuncAttributeMaxDynamicSharedMemorySize,
                         (128 * 128 + 32 * 128) * (int)sizeof(float));

    // Degrees (recomputed every call: deterministic, trivial cost)
    {
        int b = (N_NODES + 255) / 256;
        zero_deg_kernel<<<b, 256>>>();
        count_deg_kernel<<<(N_EDGES + 255) / 256, 256>>>(node_idx, hedge_idx);
        invert_deg_kernel<<<b, 256>>>();
    }

    run_layer(x,      W1, b1, p_xbuf, node_idx, hedge_idx, p_m, p_m2, p_acc, p_binv, p_dinv);
    run_layer(p_xbuf, W2, b2, p_xbuf, node_idx, hedge_idx, p_m, p_m2, p_acc, p_binv, p_dinv);
    run_layer(p_xbuf, W3, b3, out,    node_idx, hedge_idx, p_m, p_m2, p_acc, p_binv, p_dinv);
}

// round 2
// speedup vs baseline: 1.6091x; 1.6091x over previous
#include <cuda_runtime.h>
#include <math.h>

// Problem constants (fixed by the dataset)
constexpr int N_NODES = 100000;
constexpr int N_HEDGE = 25000;
constexpr int N_EDGES = 600000;
constexpr int D       = 128;

// ---------------------------------------------------------------------------
// Scratch (static __device__ arrays)
// ---------------------------------------------------------------------------
__device__ float g_m2  [N_HEDGE * D];   // (B^-1 H^T x) @ W
__device__ float g_xbuf[N_NODES * D];   // inter-layer node features
__device__ int   g_degn[N_NODES];
__device__ int   g_dege[N_HEDGE];
__device__ int   g_off_n[N_NODES];      // CSR offsets (exclusive prefix of deg)
__device__ int   g_off_e[N_HEDGE];
__device__ int   g_cur_n[N_NODES];      // fill cursors
__device__ int   g_cur_e[N_HEDGE];
__device__ int   g_adj_e[N_EDGES];      // node ids grouped by hyperedge
__device__ int   g_adj_n[N_EDGES];      // hyperedge ids grouped by node
__device__ int   g_bsum_n[512];
__device__ int   g_bsum_e[512];

// ---------------------------------------------------------------------------
// Degree histogram
// ---------------------------------------------------------------------------
__global__ void zero_deg_kernel() {
    int i = blockIdx.x * blockDim.x + threadIdx.x;
    if (i < N_NODES) g_degn[i] = 0;
    if (i < N_HEDGE) g_dege[i] = 0;
}

__global__ void count_deg_kernel(const int* __restrict__ node_idx,
                                 const int* __restrict__ hedge_idx) {
    int i = blockIdx.x * blockDim.x + threadIdx.x;
    if (i < N_EDGES) {
        atomicAdd(&g_degn[node_idx[i]], 1);
        atomicAdd(&g_dege[hedge_idx[i]], 1);
    }
}

// ---------------------------------------------------------------------------
// Two-level exclusive scan (chunks of 256; <=512 chunks)
// ---------------------------------------------------------------------------
__global__ void scan_chunk_kernel(const int* __restrict__ cnt, int n,
                                  int* __restrict__ off, int* __restrict__ bsum) {
    __shared__ int s[256];
    int i = blockIdx.x * 256 + threadIdx.x;
    int v = (i < n) ? cnt[i] : 0;
    s[threadIdx.x] = v;
    __syncthreads();
    #pragma unroll
    for (int d = 1; d < 256; d <<= 1) {
        int t = (threadIdx.x >= d) ? s[threadIdx.x - d] : 0;
        __syncthreads();
        s[threadIdx.x] += t;
        __syncthreads();
    }
    if (i < n) off[i] = s[threadIdx.x] - v;          // exclusive within chunk
    if (threadIdx.x == 255) bsum[blockIdx.x] = s[255];
}

__global__ void scan_bsum_kernel(int* __restrict__ bsum, int nb) {
    __shared__ int s[512];
    int v = (threadIdx.x < nb) ? bsum[threadIdx.x] : 0;
    s[threadIdx.x] = v;
    __syncthreads();
    #pragma unroll
    for (int d = 1; d < 512; d <<= 1) {
        int t = (threadIdx.x >= d) ? s[threadIdx.x - d] : 0;
        __syncthreads();
        s[threadIdx.x] += t;
        __syncthreads();
    }
    if (threadIdx.x < nb) bsum[threadIdx.x] = s[threadIdx.x] - v;  // exclusive
}

__global__ void scan_add_kernel(int* __restrict__ off, const int* __restrict__ bsum,
                                int n, int* __restrict__ cur) {
    int i = blockIdx.x * 256 + threadIdx.x;
    if (i < n) {
        off[i] += bsum[blockIdx.x];
        cur[i] = 0;
    }
}

// ---------------------------------------------------------------------------
// CSR fill (order within a segment is atomic-nondeterministic; sums tolerate it)
// ---------------------------------------------------------------------------
__global__ void fill_adj_kernel(const int* __restrict__ node_idx,
                                const int* __restrict__ hedge_idx) {
    int e = blockIdx.x * blockDim.x + threadIdx.x;
    if (e >= N_EDGES) return;
    int nd = node_idx[e];
    int h  = hedge_idx[e];
    int p = g_off_e[h]  + atomicAdd(&g_cur_e[h],  1);
    g_adj_e[p] = nd;
    int q = g_off_n[nd] + atomicAdd(&g_cur_n[nd], 1);
    g_adj_n[q] = h;
}

// ---------------------------------------------------------------------------
// Fused hyperedge stage: gather neighbor node rows -> B^-1 scale -> @W -> m2
// Block = 256 threads = 8 warps, 32 hyperedges per block.
// smem: W (64KB) + X tile (16KB) = 80KB -> 2 blocks/SM.
// ---------------------------------------------------------------------------
__global__ void __launch_bounds__(256)
hedge_gemm_kernel(const float* __restrict__ x, const float* __restrict__ W,
                  float* __restrict__ m2) {
    extern __shared__ float sm[];
    float* Ws = sm;              // 128*128
    float* Xs = sm + 128 * 128;  // 32*128
    int t    = threadIdx.x;
    int lane = t & 31;
    int w    = t >> 5;

    for (int i = t; i < 128 * 128 / 4; i += 256)
        ((float4*)Ws)[i] = ((const float4*)W)[i];

    int row0 = blockIdx.x * 32;

    // Phase A: gather. Warp w handles hyperedges row0 + w*4 + {0..3}.
    #pragma unroll
    for (int r = 0; r < 4; r++) {
        int h = row0 + w * 4 + r;
        float4 acc = make_float4(0.f, 0.f, 0.f, 0.f);
        if (h < N_HEDGE) {
            int start = g_off_e[h];
            int deg   = g_dege[h];
            for (int j0 = 0; j0 < deg; j0 += 32) {
                int nn  = min(32, deg - j0);
                int idx = (lane < nn) ? g_adj_e[start + j0 + lane] : 0;
                for (int k = 0; k < nn; k++) {
                    int id = __shfl_sync(0xffffffffu, idx, k);
                    float4 v = ((const float4*)(x + (size_t)id * D))[lane];
                    acc.x += v.x; acc.y += v.y; acc.z += v.z; acc.w += v.w;
                }
            }
            float s = deg > 0 ? 1.0f / (float)deg : 0.0f;
            acc.x *= s; acc.y *= s; acc.z *= s; acc.w *= s;
        }
        ((float4*)(Xs + (w * 4 + r) * 128))[lane] = acc;
    }
    __syncthreads();

    // Phase B: 32x128 @ 128x128 GEMM from smem.
    int tx = t & 31;   // cols [4*tx .. 4*tx+3]
    int ty = t >> 5;   // rows ty, ty+8, ty+16, ty+24

    float4 acc[4];
    #pragma unroll
    for (int r = 0; r < 4; r++) acc[r] = make_float4(0.f, 0.f, 0.f, 0.f);

    #pragma unroll 8
    for (int k = 0; k < 128; k++) {
        float4 wv = ((const float4*)(Ws + k * 128))[tx];
        #pragma unroll
        for (int r = 0; r < 4; r++) {
            float a = Xs[(ty + r * 8) * 128 + k];
            acc[r].x = fmaf(a, wv.x, acc[r].x);
            acc[r].y = fmaf(a, wv.y, acc[r].y);
            acc[r].z = fmaf(a, wv.z, acc[r].z);
            acc[r].w = fmaf(a, wv.w, acc[r].w);
        }
    }

    #pragma unroll
    for (int r = 0; r < 4; r++) {
        int gr = row0 + ty + r * 8;
        if (gr < N_HEDGE)
            ((float4*)(m2 + (size_t)gr * D))[tx] = acc[r];
    }
}

// ---------------------------------------------------------------------------
// Fused node stage: gather incident m2 rows -> D^-1 scale -> +bias -> ELU
// Warp per node.
// ---------------------------------------------------------------------------
__device__ __forceinline__ float elu_f(float v) {
    return v > 0.0f ? v : expm1f(v);
}

__global__ void __launch_bounds__(256)
node_gather_kernel(const float* __restrict__ m2, const float* __restrict__ bias,
                   float* __restrict__ out) {
    int gw   = (blockIdx.x * blockDim.x + threadIdx.x) >> 5;
    int lane = threadIdx.x & 31;
    if (gw >= N_NODES) return;

    int start = g_off_n[gw];
    int deg   = g_degn[gw];

    float4 acc = make_float4(0.f, 0.f, 0.f, 0.f);
    for (int j0 = 0; j0 < deg; j0 += 32) {
        int nn  = min(32, deg - j0);
        int idx = (lane < nn) ? g_adj_n[start + j0 + lane] : 0;
        for (int k = 0; k < nn; k++) {
            int id = __shfl_sync(0xffffffffu, idx, k);
            float4 v = ((const float4*)(m2 + (size_t)id * D))[lane];
            acc.x += v.x; acc.y += v.y; acc.z += v.z; acc.w += v.w;
        }
    }

    float s = deg > 0 ? 1.0f / (float)deg : 0.0f;
    float4 b = ((const float4*)bias)[lane];
    acc.x = elu_f(fmaf(acc.x, s, b.x));
    acc.y = elu_f(fmaf(acc.y, s, b.y));
    acc.z = elu_f(fmaf(acc.z, s, b.z));
    acc.w = elu_f(fmaf(acc.w, s, b.w));
    ((float4*)(out + (size_t)gw * D))[lane] = acc;
}

// ---------------------------------------------------------------------------
// Launch
// ---------------------------------------------------------------------------
extern "C" void kernel_launch(void* const* d_in, const int* in_sizes, int n_in,
                              void* d_out, int out_size) {
    const float* x  = (const float*)d_in[0];
    const float* W1 = (const float*)d_in[1];
    const float* b1 = (const float*)d_in[2];
    const float* W2 = (const float*)d_in[3];
    const float* b2 = (const float*)d_in[4];
    const float* W3 = (const float*)d_in[5];
    const float* b3 = (const float*)d_in[6];
    const int* node_idx  = (const int*)d_in[7];
    const int* hedge_idx = (const int*)d_in[8];
    float* out = (float*)d_out;

    float *p_m2, *p_xbuf;
    int *p_degn, *p_dege, *p_offn, *p_offe, *p_curn, *p_cure, *p_bn, *p_be;
    cudaGetSymbolAddress((void**)&p_m2,   g_m2);
    cudaGetSymbolAddress((void**)&p_xbuf, g_xbuf);
    cudaGetSymbolAddress((void**)&p_degn, g_degn);
    cudaGetSymbolAddress((void**)&p_dege, g_dege);
    cudaGetSymbolAddress((void**)&p_offn, g_off_n);
    cudaGetSymbolAddress((void**)&p_offe, g_off_e);
    cudaGetSymbolAddress((void**)&p_curn, g_cur_n);
    cudaGetSymbolAddress((void**)&p_cure, g_cur_e);
    cudaGetSymbolAddress((void**)&p_bn,   g_bsum_n);
    cudaGetSymbolAddress((void**)&p_be,   g_bsum_e);

    const int GEMM_SMEM = (128 * 128 + 32 * 128) * (int)sizeof(float);
    cudaFuncSetAttribute(hedge_gemm_kernel,
                         cudaFuncAttributeMaxDynamicSharedMemorySize, GEMM_SMEM);

    const int NB_N = (N_NODES + 255) / 256;   // 391 chunks
    const int NB_E = (N_HEDGE + 255) / 256;   // 98 chunks
    const int EB   = (N_EDGES + 255) / 256;

    // 1. degrees
    zero_deg_kernel<<<NB_N, 256>>>();
    count_deg_kernel<<<EB, 256>>>(node_idx, hedge_idx);

    // 2. CSR offsets (two-level exclusive scan), zero cursors
    scan_chunk_kernel<<<NB_N, 256>>>(p_degn, N_NODES, p_offn, p_bn);
    scan_chunk_kernel<<<NB_E, 256>>>(p_dege, N_HEDGE, p_offe, p_be);
    scan_bsum_kernel<<<1, 512>>>(p_bn, NB_N);
    scan_bsum_kernel<<<1, 512>>>(p_be, NB_E);
    scan_add_kernel<<<NB_N, 256>>>(p_offn, p_bn, N_NODES, p_curn);
    scan_add_kernel<<<NB_E, 256>>>(p_offe, p_be, N_HEDGE, p_cure);

    // 3. fill adjacency
    fill_adj_kernel<<<EB, 256>>>(node_idx, hedge_idx);

    // 4. three fused layers
    const int HGB = (N_HEDGE + 31) / 32;
    const int NGB = (N_NODES * 32 + 255) / 256;

    hedge_gemm_kernel<<<HGB, 256, GEMM_SMEM>>>(x, W1, p_m2);
    node_gather_kernel<<<NGB, 256>>>(p_m2, b1, p_xbuf);

    hedge_gemm_kernel<<<HGB, 256, GEMM_SMEM>>>(p_xbuf, W2, p_m2);
    node_gather_kernel<<<NGB, 256>>>(p_m2, b2, p_xbuf);

    hedge_gemm_kernel<<<HGB, 256, GEMM_SMEM>>>(p_xbuf, W3, p_m2);
    node_gather_kernel<<<NGB, 256>>>(p_m2, b3, out);
}

// round 3
// speedup vs baseline: 1.6774x; 1.0425x over previous
#include <cuda_runtime.h>
#include <math.h>

constexpr int N_NODES = 100000;
constexpr int N_HEDGE = 25000;
constexpr int N_EDGES = 600000;
constexpr int D       = 128;

constexpr int NB_N = (N_NODES + 255) / 256;   // 391
constexpr int NB_E = (N_HEDGE + 255) / 256;   // 98

// ---------------------------------------------------------------------------
// Scratch
// ---------------------------------------------------------------------------
__device__ float g_m2  [N_HEDGE * D];
__device__ float g_xbuf[N_NODES * D];
__device__ int   g_degn[N_NODES];
__device__ int   g_dege[N_HEDGE];
__device__ int   g_off_n[N_NODES];
__device__ int   g_off_e[N_HEDGE];
__device__ int   g_cur_n[N_NODES];
__device__ int   g_cur_e[N_HEDGE];
__device__ int   g_adj_e[N_EDGES];   // node ids grouped by hyperedge
__device__ int   g_adj_n[N_EDGES];   // hyperedge ids grouped by node
__device__ int   g_bsum_n[512];
__device__ int   g_bsum_e[512];

// ---------------------------------------------------------------------------
// Preproc: degrees
// ---------------------------------------------------------------------------
__global__ void zero_deg_kernel() {
    int i = blockIdx.x * blockDim.x + threadIdx.x;
    if (i < N_NODES) g_degn[i] = 0;
    if (i < N_HEDGE) g_dege[i] = 0;
}

__global__ void count_deg_kernel(const int* __restrict__ node_idx,
                                 const int* __restrict__ hedge_idx) {
    int i = blockIdx.x * blockDim.x + threadIdx.x;
    if (i < N_EDGES) {
        atomicAdd(&g_degn[node_idx[i]], 1);
        atomicAdd(&g_dege[hedge_idx[i]], 1);
    }
}

// ---------------------------------------------------------------------------
// Preproc: combined two-level scan for BOTH arrays in one launch each.
// blocks [0, NB_N) -> node array; blocks [NB_N, NB_N+NB_E) -> hedge array.
// ---------------------------------------------------------------------------
__global__ void scan_chunk_both_kernel() {
    __shared__ int s[256];
    bool is_n = blockIdx.x < NB_N;
    int blk   = is_n ? blockIdx.x : blockIdx.x - NB_N;
    const int* cnt = is_n ? g_degn : g_dege;
    int*       off = is_n ? g_off_n : g_off_e;
    int*      bsum = is_n ? g_bsum_n : g_bsum_e;
    int n          = is_n ? N_NODES : N_HEDGE;

    int i = blk * 256 + threadIdx.x;
    int v = (i < n) ? cnt[i] : 0;
    s[threadIdx.x] = v;
    __syncthreads();
    #pragma unroll
    for (int d = 1; d < 256; d <<= 1) {
        int t = (threadIdx.x >= d) ? s[threadIdx.x - d] : 0;
        __syncthreads();
        s[threadIdx.x] += t;
        __syncthreads();
    }
    if (i < n) off[i] = s[threadIdx.x] - v;
    if (threadIdx.x == 255) bsum[blk] = s[255];
}

__global__ void scan_bsum_both_kernel() {
    __shared__ int s[512];
    int* bsum = (blockIdx.x == 0) ? g_bsum_n : g_bsum_e;
    int nb    = (blockIdx.x == 0) ? NB_N : NB_E;
    int v = (threadIdx.x < nb) ? bsum[threadIdx.x] : 0;
    s[threadIdx.x] = v;
    __syncthreads();
    #pragma unroll
    for (int d = 1; d < 512; d <<= 1) {
        int t = (threadIdx.x >= d) ? s[threadIdx.x - d] : 0;
        __syncthreads();
        s[threadIdx.x] += t;
        __syncthreads();
    }
    if (threadIdx.x < nb) bsum[threadIdx.x] = s[threadIdx.x] - v;
}

// adds block base; initializes fill cursor to the final offset
__global__ void scan_add_both_kernel() {
    bool is_n = blockIdx.x < NB_N;
    int blk   = is_n ? blockIdx.x : blockIdx.x - NB_N;
    int*       off = is_n ? g_off_n : g_off_e;
    const int* bsum= is_n ? g_bsum_n : g_bsum_e;
    int*       cur = is_n ? g_cur_n : g_cur_e;
    int n          = is_n ? N_NODES : N_HEDGE;
    int i = blk * 256 + threadIdx.x;
    if (i < n) {
        int o = off[i] + bsum[blk];
        off[i] = o;
        cur[i] = o;
    }
}

__global__ void fill_adj_kernel(const int* __restrict__ node_idx,
                                const int* __restrict__ hedge_idx) {
    int e = blockIdx.x * blockDim.x + threadIdx.x;
    if (e >= N_EDGES) return;
    int nd = node_idx[e];
    int h  = hedge_idx[e];
    g_adj_e[atomicAdd(&g_cur_e[h],  1)] = nd;
    g_adj_n[atomicAdd(&g_cur_n[nd], 1)] = h;
}

// ---------------------------------------------------------------------------
// Batch-4 gather helper: sums rows src[id]*512B for ids held across the warp.
// ---------------------------------------------------------------------------
__device__ __forceinline__ void gather_rows(const float* __restrict__ src,
                                            int start, int deg, int lane,
                                            const int* __restrict__ adj,
                                            float4& acc) {
    for (int j0 = 0; j0 < deg; j0 += 32) {
        int nn  = min(32, deg - j0);
        int idx = (lane < nn) ? adj[start + j0 + lane] : 0;
        int k = 0;
        for (; k + 4 <= nn; k += 4) {
            int i0 = __shfl_sync(0xffffffffu, idx, k);
            int i1 = __shfl_sync(0xffffffffu, idx, k + 1);
            int i2 = __shfl_sync(0xffffffffu, idx, k + 2);
            int i3 = __shfl_sync(0xffffffffu, idx, k + 3);
            float4 v0 = ((const float4*)(src + (size_t)i0 * D))[lane];
            float4 v1 = ((const float4*)(src + (size_t)i1 * D))[lane];
            float4 v2 = ((const float4*)(src + (size_t)i2 * D))[lane];
            float4 v3 = ((const float4*)(src + (size_t)i3 * D))[lane];
            acc.x += (v0.x + v1.x) + (v2.x + v3.x);
            acc.y += (v0.y + v1.y) + (v2.y + v3.y);
            acc.z += (v0.z + v1.z) + (v2.z + v3.z);
            acc.w += (v0.w + v1.w) + (v2.w + v3.w);
        }
        for (; k < nn; k++) {
            int id = __shfl_sync(0xffffffffu, idx, k);
            float4 v = ((const float4*)(src + (size_t)id * D))[lane];
            acc.x += v.x; acc.y += v.y; acc.z += v.z; acc.w += v.w;
        }
    }
}

// ---------------------------------------------------------------------------
// Fused hyperedge stage: gather -> B^-1 -> @W -> m2.  32 hedges / 256-thr block.
// ---------------------------------------------------------------------------
__global__ void __launch_bounds__(256)
hedge_gemm_kernel(const float* __restrict__ x, const float* __restrict__ W,
                  float* __restrict__ m2) {
    extern __shared__ float sm[];
    float* Ws = sm;              // 128*128
    float* Xs = sm + 128 * 128;  // 32*128
    int t    = threadIdx.x;
    int lane = t & 31;
    int w    = t >> 5;

    for (int i = t; i < 128 * 128 / 4; i += 256)
        ((float4*)Ws)[i] = ((const float4*)W)[i];

    int row0 = blockIdx.x * 32;

    #pragma unroll
    for (int r = 0; r < 4; r++) {
        int h = row0 + w * 4 + r;
        float4 acc = make_float4(0.f, 0.f, 0.f, 0.f);
        if (h < N_HEDGE) {
            int start = g_off_e[h];
            int deg   = g_dege[h];
            gather_rows(x, start, deg, lane, g_adj_e, acc);
            float s = deg > 0 ? 1.0f / (float)deg : 0.0f;
            acc.x *= s; acc.y *= s; acc.z *= s; acc.w *= s;
        }
        ((float4*)(Xs + (w * 4 + r) * 128))[lane] = acc;
    }
    __syncthreads();

    int tx = t & 31;
    int ty = t >> 5;

    float4 acc[4];
    #pragma unroll
    for (int r = 0; r < 4; r++) acc[r] = make_float4(0.f, 0.f, 0.f, 0.f);

    #pragma unroll 8
    for (int k = 0; k < 128; k++) {
        float4 wv = ((const float4*)(Ws + k * 128))[tx];
        #pragma unroll
        for (int r = 0; r < 4; r++) {
            float a = Xs[(ty + r * 8) * 128 + k];
            acc[r].x = fmaf(a, wv.x, acc[r].x);
            acc[r].y = fmaf(a, wv.y, acc[r].y);
            acc[r].z = fmaf(a, wv.z, acc[r].z);
            acc[r].w = fmaf(a, wv.w, acc[r].w);
        }
    }

    #pragma unroll
    for (int r = 0; r < 4; r++) {
        int gr = row0 + ty + r * 8;
        if (gr < N_HEDGE)
            ((float4*)(m2 + (size_t)gr * D))[tx] = acc[r];
    }
}

// ---------------------------------------------------------------------------
// Fused node stage: gather incident m2 rows -> D^-1 -> +bias -> ELU
// ---------------------------------------------------------------------------
__device__ __forceinline__ float elu_f(float v) {
    return v > 0.0f ? v : expm1f(v);
}

__global__ void __launch_bounds__(256)
node_gather_kernel(const float* __restrict__ m2, const float* __restrict__ bias,
                   float* __restrict__ out) {
    int gw   = (blockIdx.x * blockDim.x + threadIdx.x) >> 5;
    int lane = threadIdx.x & 31;
    if (gw >= N_NODES) return;

    int start = g_off_n[gw];
    int deg   = g_degn[gw];

    float4 acc = make_float4(0.f, 0.f, 0.f, 0.f);
    gather_rows(m2, start, deg, lane, g_adj_n, acc);

    float s = deg > 0 ? 1.0f / (float)deg : 0.0f;
    float4 b = ((const float4*)bias)[lane];
    acc.x = elu_f(fmaf(acc.x, s, b.x));
    acc.y = elu_f(fmaf(acc.y, s, b.y));
    acc.z = elu_f(fmaf(acc.z, s, b.z));
    acc.w = elu_f(fmaf(acc.w, s, b.w));
    ((float4*)(out + (size_t)gw * D))[lane] = acc;
}

// ---------------------------------------------------------------------------
// Launch
// ---------------------------------------------------------------------------
extern "C" void kernel_launch(void* const* d_in, const int* in_sizes, int n_in,
                              void* d_out, int out_size) {
    const float* x  = (const float*)d_in[0];
    const float* W1 = (const float*)d_in[1];
    const float* b1 = (const float*)d_in[2];
    const float* W2 = (const float*)d_in[3];
    const float* b2 = (const float*)d_in[4];
    const float* W3 = (const float*)d_in[5];
    const float* b3 = (const float*)d_in[6];
    const int* node_idx  = (const int*)d_in[7];
    const int* hedge_idx = (const int*)d_in[8];
    float* out = (float*)d_out;

    float *p_m2, *p_xbuf;
    cudaGetSymbolAddress((void**)&p_m2,   g_m2);
    cudaGetSymbolAddress((void**)&p_xbuf, g_xbuf);

    const int GEMM_SMEM = (128 * 128 + 32 * 128) * (int)sizeof(float);
    cudaFuncSetAttribute(hedge_gemm_kernel,
                         cudaFuncAttributeMaxDynamicSharedMemorySize, GEMM_SMEM);

    const int EB = (N_EDGES + 255) / 256;

    // Preproc: 6 launches
    zero_deg_kernel<<<NB_N, 256>>>();
    count_deg_kernel<<<EB, 256>>>(node_idx, hedge_idx);
    scan_chunk_both_kernel<<<NB_N + NB_E, 256>>>();
    scan_bsum_both_kernel<<<2, 512>>>();
    scan_add_both_kernel<<<NB_N + NB_E, 256>>>();
    fill_adj_kernel<<<EB, 256>>>(node_idx, hedge_idx);

    // Layers
    const int HGB = (N_HEDGE + 31) / 32;
    const int NGB = (N_NODES * 32 + 255) / 256;

    hedge_gemm_kernel<<<HGB, 256, GEMM_SMEM>>>(x, W1, p_m2);
    node_gather_kernel<<<NGB, 256>>>(p_m2, b1, p_xbuf);

    hedge_gemm_kernel<<<HGB, 256, GEMM_SMEM>>>(p_xbuf, W2, p_m2);
    node_gather_kernel<<<NGB, 256>>>(p_m2, b2, p_xbuf);

    hedge_gemm_kernel<<<HGB, 256, GEMM_SMEM>>>(p_xbuf, W3, p_m2);
    node_gather_kernel<<<NGB, 256>>>(p_m2, b3, out);
}

// round 4
// speedup vs baseline: 1.7051x; 1.0165x over previous
#include <cuda_runtime.h>
#include <math.h>

constexpr int N_NODES = 100000;
constexpr int N_HEDGE = 25000;
constexpr int N_EDGES = 600000;
constexpr int D       = 128;

constexpr int NB_N = (N_NODES + 255) / 256;   // 391
constexpr int NB_E = (N_HEDGE + 255) / 256;   // 98

constexpr int N_TILES   = (N_HEDGE + 31) / 32;   // 782
constexpr int HG_BLOCKS = 296;                   // 2 per SM, persistent

// ---------------------------------------------------------------------------
// Scratch
// ---------------------------------------------------------------------------
__device__ float g_m2  [N_HEDGE * D];
__device__ float g_xbuf[N_NODES * D];
__device__ int   g_degn[N_NODES];
__device__ int   g_dege[N_HEDGE];
__device__ int   g_off_n[N_NODES];
__device__ int   g_off_e[N_HEDGE];
__device__ int   g_cur_n[N_NODES];
__device__ int   g_cur_e[N_HEDGE];
__device__ int   g_adj_e[N_EDGES];
__device__ int   g_adj_n[N_EDGES];
__device__ int   g_bsum_n[512];
__device__ int   g_bsum_e[512];

// ---------------------------------------------------------------------------
// Packed f32x2 helpers (FFMA2/FADD2 — ptxas never emits these from C++)
// ---------------------------------------------------------------------------
__device__ __forceinline__ void fma2(unsigned long long& d, unsigned long long a,
                                     unsigned long long b) {
    asm("fma.rn.f32x2 %0, %1, %2, %0;" : "+l"(d) : "l"(a), "l"(b));
}
__device__ __forceinline__ unsigned long long add2(unsigned long long a,
                                                   unsigned long long b) {
    unsigned long long d;
    asm("add.rn.f32x2 %0, %1, %2;" : "=l"(d) : "l"(a), "l"(b));
    return d;
}
__device__ __forceinline__ void adda2(unsigned long long& d, unsigned long long a) {
    asm("add.rn.f32x2 %0, %0, %1;" : "+l"(d) : "l"(a));
}
__device__ __forceinline__ unsigned long long pack2(float lo, float hi) {
    unsigned long long d;
    asm("mov.b64 %0, {%1, %2};" : "=l"(d) : "f"(lo), "f"(hi));
    return d;
}
__device__ __forceinline__ void unpack2(unsigned long long v, float& lo, float& hi) {
    asm("mov.b64 {%0, %1}, %2;" : "=f"(lo), "=f"(hi) : "l"(v));
}

// ---------------------------------------------------------------------------
// Preproc
// ---------------------------------------------------------------------------
__global__ void zero_deg_kernel() {
    int i = blockIdx.x * blockDim.x + threadIdx.x;
    if (i < N_NODES) g_degn[i] = 0;
    if (i < N_HEDGE) g_dege[i] = 0;
}

__global__ void count_deg_kernel(const int* __restrict__ node_idx,
                                 const int* __restrict__ hedge_idx) {
    int i = blockIdx.x * blockDim.x + threadIdx.x;
    if (i < N_EDGES) {
        atomicAdd(&g_degn[node_idx[i]], 1);
        atomicAdd(&g_dege[hedge_idx[i]], 1);
    }
}

__global__ void scan_chunk_both_kernel() {
    __shared__ int s[256];
    bool is_n = blockIdx.x < NB_N;
    int blk   = is_n ? blockIdx.x : blockIdx.x - NB_N;
    const int* cnt = is_n ? g_degn : g_dege;
    int*       off = is_n ? g_off_n : g_off_e;
    int*      bsum = is_n ? g_bsum_n : g_bsum_e;
    int n          = is_n ? N_NODES : N_HEDGE;

    int i = blk * 256 + threadIdx.x;
    int v = (i < n) ? cnt[i] : 0;
    s[threadIdx.x] = v;
    __syncthreads();
    #pragma unroll
    for (int d = 1; d < 256; d <<= 1) {
        int t = (threadIdx.x >= d) ? s[threadIdx.x - d] : 0;
        __syncthreads();
        s[threadIdx.x] += t;
        __syncthreads();
    }
    if (i < n) off[i] = s[threadIdx.x] - v;
    if (threadIdx.x == 255) bsum[blk] = s[255];
}

__global__ void scan_bsum_both_kernel() {
    __shared__ int s[512];
    int* bsum = (blockIdx.x == 0) ? g_bsum_n : g_bsum_e;
    int nb    = (blockIdx.x == 0) ? NB_N : NB_E;
    int v = (threadIdx.x < nb) ? bsum[threadIdx.x] : 0;
    s[threadIdx.x] = v;
    __syncthreads();
    #pragma unroll
    for (int d = 1; d < 512; d <<= 1) {
        int t = (threadIdx.x >= d) ? s[threadIdx.x - d] : 0;
        __syncthreads();
        s[threadIdx.x] += t;
        __syncthreads();
    }
    if (threadIdx.x < nb) bsum[threadIdx.x] = s[threadIdx.x] - v;
}

__global__ void scan_add_both_kernel() {
    bool is_n = blockIdx.x < NB_N;
    int blk   = is_n ? blockIdx.x : blockIdx.x - NB_N;
    int*       off = is_n ? g_off_n : g_off_e;
    const int* bsum= is_n ? g_bsum_n : g_bsum_e;
    int*       cur = is_n ? g_cur_n : g_cur_e;
    int n          = is_n ? N_NODES : N_HEDGE;
    int i = blk * 256 + threadIdx.x;
    if (i < n) {
        int o = off[i] + bsum[blk];
        off[i] = o;
        cur[i] = o;
    }
}

__global__ void fill_adj_kernel(const int* __restrict__ node_idx,
                                const int* __restrict__ hedge_idx) {
    int e = blockIdx.x * blockDim.x + threadIdx.x;
    if (e >= N_EDGES) return;
    int nd = node_idx[e];
    int h  = hedge_idx[e];
    g_adj_e[atomicAdd(&g_cur_e[h],  1)] = nd;
    g_adj_n[atomicAdd(&g_cur_n[nd], 1)] = h;
}

// ---------------------------------------------------------------------------
// Gather helper: batch-4 loads, packed f32x2 accumulation.
// acc = {acc01, acc23} packed pairs of the lane's float4 slot.
// ---------------------------------------------------------------------------
__device__ __forceinline__ void gather_rows_p(const float* __restrict__ src,
                                              int start, int deg, int lane,
                                              const int* __restrict__ adj,
                                              unsigned long long& acc01,
                                              unsigned long long& acc23) {
    for (int j0 = 0; j0 < deg; j0 += 32) {
        int nn  = min(32, deg - j0);
        int idx = (lane < nn) ? adj[start + j0 + lane] : 0;
        int k = 0;
        for (; k + 4 <= nn; k += 4) {
            int i0 = __shfl_sync(0xffffffffu, idx, k);
            int i1 = __shfl_sync(0xffffffffu, idx, k + 1);
            int i2 = __shfl_sync(0xffffffffu, idx, k + 2);
            int i3 = __shfl_sync(0xffffffffu, idx, k + 3);
            ulonglong2 v0 = ((const ulonglong2*)(src + (size_t)i0 * D))[lane];
            ulonglong2 v1 = ((const ulonglong2*)(src + (size_t)i1 * D))[lane];
            ulonglong2 v2 = ((const ulonglong2*)(src + (size_t)i2 * D))[lane];
            ulonglong2 v3 = ((const ulonglong2*)(src + (size_t)i3 * D))[lane];
            adda2(acc01, add2(add2(v0.x, v1.x), add2(v2.x, v3.x)));
            adda2(acc23, add2(add2(v0.y, v1.y), add2(v2.y, v3.y)));
        }
        for (; k < nn; k++) {
            int id = __shfl_sync(0xffffffffu, idx, k);
            ulonglong2 v = ((const ulonglong2*)(src + (size_t)id * D))[lane];
            adda2(acc01, v.x);
            adda2(acc23, v.y);
        }
    }
}

// ---------------------------------------------------------------------------
// Persistent fused hyperedge stage: gather -> B^-1 -> @W (f32x2) -> m2
// Grid = 296 blocks (2/SM); each block loads W once and loops over 32-row tiles.
// ---------------------------------------------------------------------------
__global__ void __launch_bounds__(256)
hedge_gemm_kernel(const float* __restrict__ x, const float* __restrict__ W,
                  float* __restrict__ m2) {
    extern __shared__ float sm[];
    float* Ws = sm;              // 128*128
    float* Xs = sm + 128 * 128;  // 32*128
    int t    = threadIdx.x;
    int lane = t & 31;
    int w    = t >> 5;
    int tx = t & 31;
    int ty = t >> 5;

    for (int i = t; i < 128 * 128 / 4; i += 256)
        ((float4*)Ws)[i] = ((const float4*)W)[i];
    __syncthreads();

    for (int tile = blockIdx.x; tile < N_TILES; tile += HG_BLOCKS) {
        int row0 = tile * 32;

        // Phase A: gather 4 hyperedge rows per warp into Xs
        #pragma unroll
        for (int r = 0; r < 4; r++) {
            int h = row0 + w * 4 + r;
            unsigned long long a01 = 0, a23 = 0;   // +0.0f pairs
            if (h < N_HEDGE) {
                int start = g_off_e[h];
                int deg   = g_dege[h];
                gather_rows_p(x, start, deg, lane, g_adj_e, a01, a23);
                float s = deg > 0 ? 1.0f / (float)deg : 0.0f;
                float x0, x1, x2, x3;
                unpack2(a01, x0, x1);
                unpack2(a23, x2, x3);
                a01 = pack2(x0 * s, x1 * s);
                a23 = pack2(x2 * s, x3 * s);
            }
            ((ulonglong2*)(Xs + (w * 4 + r) * 128))[lane] = make_ulonglong2(a01, a23);
        }
        __syncthreads();

        // Phase B: 32x128 @ 128x128, packed f32x2 FMA
        unsigned long long acc01[4], acc23[4];
        #pragma unroll
        for (int r = 0; r < 4; r++) { acc01[r] = 0ull; acc23[r] = 0ull; }

        #pragma unroll 4
        for (int k = 0; k < 128; k++) {
            ulonglong2 wv = ((const ulonglong2*)(Ws + k * 128))[tx];
            #pragma unroll
            for (int r = 0; r < 4; r++) {
                float a = Xs[(ty + r * 8) * 128 + k];
                unsigned long long aa = pack2(a, a);
                fma2(acc01[r], aa, wv.x);
                fma2(acc23[r], aa, wv.y);
            }
        }

        #pragma unroll
        for (int r = 0; r < 4; r++) {
            int gr = row0 + ty + r * 8;
            if (gr < N_HEDGE)
                ((ulonglong2*)(m2 + (size_t)gr * D))[tx] =
                    make_ulonglong2(acc01[r], acc23[r]);
        }
        __syncthreads();   // protect Xs before next tile's gather
    }
}

// ---------------------------------------------------------------------------
// Fused node stage: gather incident m2 rows -> D^-1 -> +bias -> ELU
// ---------------------------------------------------------------------------
__device__ __forceinline__ float elu_f(float v) {
    return v > 0.0f ? v : expm1f(v);
}

__global__ void __launch_bounds__(256)
node_gather_kernel(const float* __restrict__ m2, const float* __restrict__ bias,
                   float* __restrict__ out) {
    int gw   = (blockIdx.x * blockDim.x + threadIdx.x) >> 5;
    int lane = threadIdx.x & 31;
    if (gw >= N_NODES) return;

    int start = g_off_n[gw];
    int deg   = g_degn[gw];

    unsigned long long a01 = 0, a23 = 0;
    gather_rows_p(m2, start, deg, lane, g_adj_n, a01, a23);

    float s = deg > 0 ? 1.0f / (float)deg : 0.0f;
    float4 b = ((const float4*)bias)[lane];
    float v0, v1, v2, v3;
    unpack2(a01, v0, v1);
    unpack2(a23, v2, v3);
    float4 o;
    o.x = elu_f(fmaf(v0, s, b.x));
    o.y = elu_f(fmaf(v1, s, b.y));
    o.z = elu_f(fmaf(v2, s, b.z));
    o.w = elu_f(fmaf(v3, s, b.w));
    ((float4*)(out + (size_t)gw * D))[lane] = o;
}

// ---------------------------------------------------------------------------
// Launch
// ---------------------------------------------------------------------------
extern "C" void kernel_launch(void* const* d_in, const int* in_sizes, int n_in,
                              void* d_out, int out_size) {
    const float* x  = (const float*)d_in[0];
    const float* W1 = (const float*)d_in[1];
    const float* b1 = (const float*)d_in[2];
    const float* W2 = (const float*)d_in[3];
    const float* b2 = (const float*)d_in[4];
    const float* W3 = (const float*)d_in[5];
    const float* b3 = (const float*)d_in[6];
    const int* node_idx  = (const int*)d_in[7];
    const int* hedge_idx = (const int*)d_in[8];
    float* out = (float*)d_out;

    float *p_m2, *p_xbuf;
    cudaGetSymbolAddress((void**)&p_m2,   g_m2);
    cudaGetSymbolAddress((void**)&p_xbuf, g_xbuf);

    const int GEMM_SMEM = (128 * 128 + 32 * 128) * (int)sizeof(float);
    cudaFuncSetAttribute(hedge_gemm_kernel,
                         cudaFuncAttributeMaxDynamicSharedMemorySize, GEMM_SMEM);

    const int EB = (N_EDGES + 255) / 256;

    zero_deg_kernel<<<NB_N, 256>>>();
    count_deg_kernel<<<EB, 256>>>(node_idx, hedge_idx);
    scan_chunk_both_kernel<<<NB_N + NB_E, 256>>>();
    scan_bsum_both_kernel<<<2, 512>>>();
    scan_add_both_kernel<<<NB_N + NB_E, 256>>>();
    fill_adj_kernel<<<EB, 256>>>(node_idx, hedge_idx);

    const int NGB = (N_NODES * 32 + 255) / 256;

    hedge_gemm_kernel<<<HG_BLOCKS, 256, GEMM_SMEM>>>(x, W1, p_m2);
    node_gather_kernel<<<NGB, 256>>>(p_m2, b1, p_xbuf);

    hedge_gemm_kernel<<<HG_BLOCKS, 256, GEMM_SMEM>>>(p_xbuf, W2, p_m2);
    node_gather_kernel<<<NGB, 256>>>(p_m2, b2, p_xbuf);

    hedge_gemm_kernel<<<HG_BLOCKS, 256, GEMM_SMEM>>>(p_xbuf, W3, p_m2);
    node_gather_kernel<<<NGB, 256>>>(p_m2, b3, out);
}

// round 5
// speedup vs baseline: 1.8718x; 1.0978x over previous
#include <cuda_runtime.h>
#include <cuda_fp16.h>
#include <math.h>

constexpr int N_NODES = 100000;
constexpr int N_HEDGE = 25000;
constexpr int N_EDGES = 600000;
constexpr int D       = 128;

constexpr int NB_N = (N_NODES + 255) / 256;   // 391
constexpr int NB_E = (N_HEDGE + 255) / 256;   // 98

constexpr int N_TILES   = (N_HEDGE + 31) / 32;   // 782
constexpr int HG_BLOCKS = 296;                   // 2 per SM, persistent

// ---------------------------------------------------------------------------
// Scratch
// ---------------------------------------------------------------------------
__device__ __half g_xh [N_NODES * D];   // fp16 node features (input to hedge gather)
__device__ __half g_m2h[N_HEDGE * D];   // fp16 (B^-1 H^T x) @ W
__device__ int   g_degn[N_NODES];
__device__ int   g_dege[N_HEDGE];
__device__ int   g_off_n[N_NODES];
__device__ int   g_off_e[N_HEDGE];
__device__ int   g_cur_n[N_NODES];
__device__ int   g_cur_e[N_HEDGE];
__device__ int   g_adj_e[N_EDGES];
__device__ int   g_adj_n[N_EDGES];
__device__ int   g_bsum_n[512];
__device__ int   g_bsum_e[512];

// ---------------------------------------------------------------------------
// Packed f32x2 helpers
// ---------------------------------------------------------------------------
__device__ __forceinline__ void fma2(unsigned long long& d, unsigned long long a,
                                     unsigned long long b) {
    asm("fma.rn.f32x2 %0, %1, %2, %0;" : "+l"(d) : "l"(a), "l"(b));
}
__device__ __forceinline__ unsigned long long pack2(float lo, float hi) {
    unsigned long long d;
    asm("mov.b64 %0, {%1, %2};" : "=l"(d) : "f"(lo), "f"(hi));
    return d;
}
__device__ __forceinline__ void unpack2(unsigned long long v, float& lo, float& hi) {
    asm("mov.b64 {%0, %1}, %2;" : "=f"(lo), "=f"(hi) : "l"(v));
}

// ---------------------------------------------------------------------------
// Preproc
// ---------------------------------------------------------------------------
__global__ void zero_deg_kernel() {
    int i = blockIdx.x * blockDim.x + threadIdx.x;
    if (i < N_NODES) g_degn[i] = 0;
    if (i < N_HEDGE) g_dege[i] = 0;
}

__global__ void count_deg_kernel(const int* __restrict__ node_idx,
                                 const int* __restrict__ hedge_idx) {
    int i = blockIdx.x * blockDim.x + threadIdx.x;
    if (i < N_EDGES) {
        atomicAdd(&g_degn[node_idx[i]], 1);
        atomicAdd(&g_dege[hedge_idx[i]], 1);
    }
}

__global__ void scan_chunk_both_kernel() {
    __shared__ int s[256];
    bool is_n = blockIdx.x < NB_N;
    int blk   = is_n ? blockIdx.x : blockIdx.x - NB_N;
    const int* cnt = is_n ? g_degn : g_dege;
    int*       off = is_n ? g_off_n : g_off_e;
    int*      bsum = is_n ? g_bsum_n : g_bsum_e;
    int n          = is_n ? N_NODES : N_HEDGE;

    int i = blk * 256 + threadIdx.x;
    int v = (i < n) ? cnt[i] : 0;
    s[threadIdx.x] = v;
    __syncthreads();
    #pragma unroll
    for (int d = 1; d < 256; d <<= 1) {
        int t = (threadIdx.x >= d) ? s[threadIdx.x - d] : 0;
        __syncthreads();
        s[threadIdx.x] += t;
        __syncthreads();
    }
    if (i < n) off[i] = s[threadIdx.x] - v;
    if (threadIdx.x == 255) bsum[blk] = s[255];
}

__global__ void scan_bsum_both_kernel() {
    __shared__ int s[512];
    int* bsum = (blockIdx.x == 0) ? g_bsum_n : g_bsum_e;
    int nb    = (blockIdx.x == 0) ? NB_N : NB_E;
    int v = (threadIdx.x < nb) ? bsum[threadIdx.x] : 0;
    s[threadIdx.x] = v;
    __syncthreads();
    #pragma unroll
    for (int d = 1; d < 512; d <<= 1) {
        int t = (threadIdx.x >= d) ? s[threadIdx.x - d] : 0;
        __syncthreads();
        s[threadIdx.x] += t;
        __syncthreads();
    }
    if (threadIdx.x < nb) bsum[threadIdx.x] = s[threadIdx.x] - v;
}

__global__ void scan_add_both_kernel() {
    bool is_n = blockIdx.x < NB_N;
    int blk   = is_n ? blockIdx.x : blockIdx.x - NB_N;
    int*       off = is_n ? g_off_n : g_off_e;
    const int* bsum= is_n ? g_bsum_n : g_bsum_e;
    int*       cur = is_n ? g_cur_n : g_cur_e;
    int n          = is_n ? N_NODES : N_HEDGE;
    int i = blk * 256 + threadIdx.x;
    if (i < n) {
        int o = off[i] + bsum[blk];
        off[i] = o;
        cur[i] = o;
    }
}

__global__ void fill_adj_kernel(const int* __restrict__ node_idx,
                                const int* __restrict__ hedge_idx) {
    int e = blockIdx.x * blockDim.x + threadIdx.x;
    if (e >= N_EDGES) return;
    int nd = node_idx[e];
    int h  = hedge_idx[e];
    g_adj_e[atomicAdd(&g_cur_e[h],  1)] = nd;
    g_adj_n[atomicAdd(&g_cur_n[nd], 1)] = h;
}

// ---------------------------------------------------------------------------
// Convert x fp32 -> fp16 (once per call)
// ---------------------------------------------------------------------------
__global__ void convert_x_kernel(const float* __restrict__ x) {
    int i = blockIdx.x * blockDim.x + threadIdx.x;   // over N*D/4 float4s
    if (i >= N_NODES * D / 4) return;
    float4 v = ((const float4*)x)[i];
    __half2 h0 = __floats2half2_rn(v.x, v.y);
    __half2 h1 = __floats2half2_rn(v.z, v.w);
    ((__half2*)g_xh)[i * 2]     = h0;
    ((__half2*)g_xh)[i * 2 + 1] = h1;
}

// ---------------------------------------------------------------------------
// fp16 gather: each lane owns 4 half columns (8B) of a 256B row.
// Batch-4 neighbor rows, fp32 accumulation.
// ---------------------------------------------------------------------------
__device__ __forceinline__ void acc_row(uint2 v, float2& a0, float2& a1) {
    float2 f0 = __half22float2(*(const __half2*)&v.x);
    float2 f1 = __half22float2(*(const __half2*)&v.y);
    a0.x += f0.x; a0.y += f0.y;
    a1.x += f1.x; a1.y += f1.y;
}

__device__ __forceinline__ void gather_rows_h(const __half* __restrict__ src,
                                              int start, int deg, int lane,
                                              const int* __restrict__ adj,
                                              float2& a0, float2& a1) {
    for (int j0 = 0; j0 < deg; j0 += 32) {
        int nn  = min(32, deg - j0);
        int idx = (lane < nn) ? adj[start + j0 + lane] : 0;
        int k = 0;
        for (; k + 4 <= nn; k += 4) {
            int i0 = __shfl_sync(0xffffffffu, idx, k);
            int i1 = __shfl_sync(0xffffffffu, idx, k + 1);
            int i2 = __shfl_sync(0xffffffffu, idx, k + 2);
            int i3 = __shfl_sync(0xffffffffu, idx, k + 3);
            uint2 v0 = ((const uint2*)(src + (size_t)i0 * D))[lane];
            uint2 v1 = ((const uint2*)(src + (size_t)i1 * D))[lane];
            uint2 v2 = ((const uint2*)(src + (size_t)i2 * D))[lane];
            uint2 v3 = ((const uint2*)(src + (size_t)i3 * D))[lane];
            acc_row(v0, a0, a1);
            acc_row(v1, a0, a1);
            acc_row(v2, a0, a1);
            acc_row(v3, a0, a1);
        }
        for (; k < nn; k++) {
            int id = __shfl_sync(0xffffffffu, idx, k);
            uint2 v = ((const uint2*)(src + (size_t)id * D))[lane];
            acc_row(v, a0, a1);
        }
    }
}

// ---------------------------------------------------------------------------
// Persistent fused hyperedge stage: fp16 gather -> B^-1 -> fp32 GEMM -> fp16 m2
// Lane layout note: gather lane owns halfs [4*lane .. 4*lane+3] of the row; it
// writes those to Xs[.. ] fp32, so Xs is the exact fp32 row. GEMM as before.
// ---------------------------------------------------------------------------
__global__ void __launch_bounds__(256)
hedge_gemm_kernel(const __half* __restrict__ xh, const float* __restrict__ W,
                  __half* __restrict__ m2h) {
    extern __shared__ float sm[];
    float* Ws = sm;              // 128*128
    float* Xs = sm + 128 * 128;  // 32*128
    int t    = threadIdx.x;
    int lane = t & 31;
    int w    = t >> 5;
    int tx = t & 31;
    int ty = t >> 5;

    for (int i = t; i < 128 * 128 / 4; i += 256)
        ((float4*)Ws)[i] = ((const float4*)W)[i];
    __syncthreads();

    for (int tile = blockIdx.x; tile < N_TILES; tile += HG_BLOCKS) {
        int row0 = tile * 32;

        #pragma unroll
        for (int r = 0; r < 4; r++) {
            int h = row0 + w * 4 + r;
            float2 a0 = make_float2(0.f, 0.f);
            float2 a1 = make_float2(0.f, 0.f);
            if (h < N_HEDGE) {
                int start = g_off_e[h];
                int deg   = g_dege[h];
                gather_rows_h(xh, start, deg, lane, g_adj_e, a0, a1);
                float s = deg > 0 ? 1.0f / (float)deg : 0.0f;
                a0.x *= s; a0.y *= s; a1.x *= s; a1.y *= s;
            }
            ((float4*)(Xs + (w * 4 + r) * 128))[lane] =
                make_float4(a0.x, a0.y, a1.x, a1.y);
        }
        __syncthreads();

        // 32x128 @ 128x128 fp32 GEMM (f32x2 FMA)
        unsigned long long acc01[4], acc23[4];
        #pragma unroll
        for (int r = 0; r < 4; r++) { acc01[r] = 0ull; acc23[r] = 0ull; }

        #pragma unroll 4
        for (int k = 0; k < 128; k++) {
            ulonglong2 wv = ((const ulonglong2*)(Ws + k * 128))[tx];
            #pragma unroll
            for (int r = 0; r < 4; r++) {
                float a = Xs[(ty + r * 8) * 128 + k];
                unsigned long long aa = pack2(a, a);
                fma2(acc01[r], aa, wv.x);
                fma2(acc23[r], aa, wv.y);
            }
        }

        #pragma unroll
        for (int r = 0; r < 4; r++) {
            int gr = row0 + ty + r * 8;
            if (gr < N_HEDGE) {
                float c0, c1, c2, c3;
                unpack2(acc01[r], c0, c1);
                unpack2(acc23[r], c2, c3);
                __half2 h0 = __floats2half2_rn(c0, c1);
                __half2 h1 = __floats2half2_rn(c2, c3);
                uint2 pv;
                pv.x = *(unsigned int*)&h0;
                pv.y = *(unsigned int*)&h1;
                ((uint2*)(m2h + (size_t)gr * D))[tx] = pv;
            }
        }
        __syncthreads();
    }
}

// ---------------------------------------------------------------------------
// Fused node stage: fp16 gather of m2 rows -> D^-1 -> +bias -> ELU
// LAST=false: write fp16 to g_xh (next layer input). LAST=true: fp32 to out.
// ---------------------------------------------------------------------------
__device__ __forceinline__ float elu_f(float v) {
    return v > 0.0f ? v : expm1f(v);
}

template <bool LAST>
__global__ void __launch_bounds__(256)
node_gather_kernel(const __half* __restrict__ m2h, const float* __restrict__ bias,
                   float* __restrict__ out) {
    int gw   = (blockIdx.x * blockDim.x + threadIdx.x) >> 5;
    int lane = threadIdx.x & 31;
    if (gw >= N_NODES) return;

    int start = g_off_n[gw];
    int deg   = g_degn[gw];

    float2 a0 = make_float2(0.f, 0.f);
    float2 a1 = make_float2(0.f, 0.f);
    gather_rows_h(m2h, start, deg, lane, g_adj_n, a0, a1);

    float s = deg > 0 ? 1.0f / (float)deg : 0.0f;
    float4 b = ((const float4*)bias)[lane];
    float v0 = elu_f(fmaf(a0.x, s, b.x));
    float v1 = elu_f(fmaf(a0.y, s, b.y));
    float v2 = elu_f(fmaf(a1.x, s, b.z));
    float v3 = elu_f(fmaf(a1.y, s, b.w));

    if (LAST) {
        ((float4*)(out + (size_t)gw * D))[lane] = make_float4(v0, v1, v2, v3);
    } else {
        __half2 h0 = __floats2half2_rn(v0, v1);
        __half2 h1 = __floats2half2_rn(v2, v3);
        uint2 pv;
        pv.x = *(unsigned int*)&h0;
        pv.y = *(unsigned int*)&h1;
        ((uint2*)(g_xh + (size_t)gw * D))[lane] = pv;
    }
}

// ---------------------------------------------------------------------------
// Launch
// ---------------------------------------------------------------------------
extern "C" void kernel_launch(void* const* d_in, const int* in_sizes, int n_in,
                              void* d_out, int out_size) {
    const float* x  = (const float*)d_in[0];
    const float* W1 = (const float*)d_in[1];
    const float* b1 = (const float*)d_in[2];
    const float* W2 = (const float*)d_in[3];
    const float* b2 = (const float*)d_in[4];
    const float* W3 = (const float*)d_in[5];
    const float* b3 = (const float*)d_in[6];
    const int* node_idx  = (const int*)d_in[7];
    const int* hedge_idx = (const int*)d_in[8];
    float* out = (float*)d_out;

    __half *p_xh, *p_m2h;
    cudaGetSymbolAddress((void**)&p_xh,  g_xh);
    cudaGetSymbolAddress((void**)&p_m2h, g_m2h);

    const int GEMM_SMEM = (128 * 128 + 32 * 128) * (int)sizeof(float);
    cudaFuncSetAttribute(hedge_gemm_kernel,
                         cudaFuncAttributeMaxDynamicSharedMemorySize, GEMM_SMEM);

    const int EB = (N_EDGES + 255) / 256;

    zero_deg_kernel<<<NB_N, 256>>>();
    count_deg_kernel<<<EB, 256>>>(node_idx, hedge_idx);
    scan_chunk_both_kernel<<<NB_N + NB_E, 256>>>();
    scan_bsum_both_kernel<<<2, 512>>>();
    scan_add_both_kernel<<<NB_N + NB_E, 256>>>();
    fill_adj_kernel<<<EB, 256>>>(node_idx, hedge_idx);

    convert_x_kernel<<<(N_NODES * D / 4 + 255) / 256, 256>>>(x);

    const int NGB = (N_NODES * 32 + 255) / 256;

    hedge_gemm_kernel<<<HG_BLOCKS, 256, GEMM_SMEM>>>(p_xh, W1, p_m2h);
    node_gather_kernel<false><<<NGB, 256>>>(p_m2h, b1, nullptr);

    hedge_gemm_kernel<<<HG_BLOCKS, 256, GEMM_SMEM>>>(p_xh, W2, p_m2h);
    node_gather_kernel<false><<<NGB, 256>>>(p_m2h, b2, nullptr);

    hedge_gemm_kernel<<<HG_BLOCKS, 256, GEMM_SMEM>>>(p_xh, W3, p_m2h);
    node_gather_kernel<true><<<NGB, 256>>>(p_m2h, b3, out);
}

// round 7
// speedup vs baseline: 2.2082x; 1.1798x over previous
#include <cuda_runtime.h>
#include <cuda_fp16.h>
#include <math.h>

constexpr int N_NODES = 100000;
constexpr int N_HEDGE = 25000;
constexpr int N_EDGES = 600000;
constexpr int D       = 128;

constexpr int NB_N = (N_NODES + 255) / 256;   // 391
constexpr int NB_E = (N_HEDGE + 255) / 256;   // 98

// ---------------------------------------------------------------------------
// Scratch
// ---------------------------------------------------------------------------
__device__ __half g_xh [N_NODES * D];
__device__ __half g_m2h[N_HEDGE * D];
__device__ int   g_degn[N_NODES];
__device__ int   g_dege[N_HEDGE];
__device__ int   g_off_n[N_NODES];
__device__ int   g_off_e[N_HEDGE];
__device__ int   g_cur_n[N_NODES];
__device__ int   g_cur_e[N_HEDGE];
__device__ int   g_adj_e[N_EDGES];
__device__ int   g_adj_n[N_EDGES];
__device__ int   g_bsum_n[512];
__device__ int   g_bsum_e[512];

// ---------------------------------------------------------------------------
// Packed f32x2 helpers
// ---------------------------------------------------------------------------
__device__ __forceinline__ void fma2(unsigned long long& d, unsigned long long a,
                                     unsigned long long b) {
    asm("fma.rn.f32x2 %0, %1, %2, %0;" : "+l"(d) : "l"(a), "l"(b));
}
__device__ __forceinline__ unsigned long long pack2(float lo, float hi) {
    unsigned long long d;
    asm("mov.b64 %0, {%1, %2};" : "=l"(d) : "f"(lo), "f"(hi));
    return d;
}
__device__ __forceinline__ void unpack2(unsigned long long v, float& lo, float& hi) {
    asm("mov.b64 {%0, %1}, %2;" : "=f"(lo), "=f"(hi) : "l"(v));
}

// ---------------------------------------------------------------------------
// Preproc
// ---------------------------------------------------------------------------
__global__ void zero_deg_kernel() {
    int i = blockIdx.x * blockDim.x + threadIdx.x;
    if (i < N_NODES) g_degn[i] = 0;
    if (i < N_HEDGE) g_dege[i] = 0;
}

__global__ void count_deg_kernel(const int* __restrict__ node_idx,
                                 const int* __restrict__ hedge_idx) {
    int i = blockIdx.x * blockDim.x + threadIdx.x;
    if (i < N_EDGES) {
        atomicAdd(&g_degn[node_idx[i]], 1);
        atomicAdd(&g_dege[hedge_idx[i]], 1);
    }
}

__global__ void scan_chunk_both_kernel() {
    __shared__ int s[256];
    bool is_n = blockIdx.x < NB_N;
    int blk   = is_n ? blockIdx.x : blockIdx.x - NB_N;
    const int* cnt = is_n ? g_degn : g_dege;
    int*       off = is_n ? g_off_n : g_off_e;
    int*      bsum = is_n ? g_bsum_n : g_bsum_e;
    int n          = is_n ? N_NODES : N_HEDGE;

    int i = blk * 256 + threadIdx.x;
    int v = (i < n) ? cnt[i] : 0;
    s[threadIdx.x] = v;
    __syncthreads();
    #pragma unroll
    for (int d = 1; d < 256; d <<= 1) {
        int t = (threadIdx.x >= d) ? s[threadIdx.x - d] : 0;
        __syncthreads();
        s[threadIdx.x] += t;
        __syncthreads();
    }
    if (i < n) off[i] = s[threadIdx.x] - v;
    if (threadIdx.x == 255) bsum[blk] = s[255];
}

__global__ void scan_bsum_both_kernel() {
    __shared__ int s[512];
    int* bsum = (blockIdx.x == 0) ? g_bsum_n : g_bsum_e;
    int nb    = (blockIdx.x == 0) ? NB_N : NB_E;
    int v = (threadIdx.x < nb) ? bsum[threadIdx.x] : 0;
    s[threadIdx.x] = v;
    __syncthreads();
    #pragma unroll
    for (int d = 1; d < 512; d <<= 1) {
        int t = (threadIdx.x >= d) ? s[threadIdx.x - d] : 0;
        __syncthreads();
        s[threadIdx.x] += t;
        __syncthreads();
    }
    if (threadIdx.x < nb) bsum[threadIdx.x] = s[threadIdx.x] - v;
}

__global__ void scan_add_both_kernel() {
    bool is_n = blockIdx.x < NB_N;
    int blk   = is_n ? blockIdx.x : blockIdx.x - NB_N;
    int*       off = is_n ? g_off_n : g_off_e;
    const int* bsum= is_n ? g_bsum_n : g_bsum_e;
    int*       cur = is_n ? g_cur_n : g_cur_e;
    int n          = is_n ? N_NODES : N_HEDGE;
    int i = blk * 256 + threadIdx.x;
    if (i < n) {
        int o = off[i] + bsum[blk];
        off[i] = o;
        cur[i] = o;
    }
}

__global__ void fill_adj_kernel(const int* __restrict__ node_idx,
                                const int* __restrict__ hedge_idx) {
    int e = blockIdx.x * blockDim.x + threadIdx.x;
    if (e >= N_EDGES) return;
    int nd = node_idx[e];
    int h  = hedge_idx[e];
    g_adj_e[atomicAdd(&g_cur_e[h],  1)] = nd;
    g_adj_n[atomicAdd(&g_cur_n[nd], 1)] = h;
}

__global__ void convert_x_kernel(const float* __restrict__ x) {
    int i = blockIdx.x * blockDim.x + threadIdx.x;
    if (i >= N_NODES * D / 4) return;
    float4 v = ((const float4*)x)[i];
    __half2 h0 = __floats2half2_rn(v.x, v.y);
    __half2 h1 = __floats2half2_rn(v.z, v.w);
    ((__half2*)g_xh)[i * 2]     = h0;
    ((__half2*)g_xh)[i * 2 + 1] = h1;
}

// ---------------------------------------------------------------------------
// Half-warp gather: 16 lanes own a 256B fp16 row (uint4 = 8 halfs each).
// mask = this half-warp's lane mask; all shuffles are HALF-warp collective so
// the two halves of a warp may run different trip counts without deadlock.
// ---------------------------------------------------------------------------
__device__ __forceinline__ void acc_row16(uint4 v, float2* a) {
    float2 f0 = __half22float2(*(const __half2*)&v.x);
    float2 f1 = __half22float2(*(const __half2*)&v.y);
    float2 f2 = __half22float2(*(const __half2*)&v.z);
    float2 f3 = __half22float2(*(const __half2*)&v.w);
    a[0].x += f0.x; a[0].y += f0.y;
    a[1].x += f1.x; a[1].y += f1.y;
    a[2].x += f2.x; a[2].y += f2.y;
    a[3].x += f3.x; a[3].y += f3.y;
}

__device__ __forceinline__ void gather_rows16(const __half* __restrict__ src,
                                              int start, int deg,
                                              unsigned mask, int base, int l16,
                                              const int* __restrict__ adj,
                                              float2* a) {
    for (int j0 = 0; j0 < deg; j0 += 16) {
        int nn  = min(16, deg - j0);
        int idx = (l16 < nn) ? adj[start + j0 + l16] : 0;
        int k = 0;
        for (; k + 4 <= nn; k += 4) {
            int i0 = __shfl_sync(mask, idx, base + k);
            int i1 = __shfl_sync(mask, idx, base + k + 1);
            int i2 = __shfl_sync(mask, idx, base + k + 2);
            int i3 = __shfl_sync(mask, idx, base + k + 3);
            uint4 v0 = ((const uint4*)(src + (size_t)i0 * D))[l16];
            uint4 v1 = ((const uint4*)(src + (size_t)i1 * D))[l16];
            uint4 v2 = ((const uint4*)(src + (size_t)i2 * D))[l16];
            uint4 v3 = ((const uint4*)(src + (size_t)i3 * D))[l16];
            acc_row16(v0, a);
            acc_row16(v1, a);
            acc_row16(v2, a);
            acc_row16(v3, a);
        }
        for (; k < nn; k++) {
            int id = __shfl_sync(mask, idx, base + k);
            uint4 v = ((const uint4*)(src + (size_t)id * D))[l16];
            acc_row16(v, a);
        }
    }
}

// ---------------------------------------------------------------------------
// Fused hyperedge stage: 512 threads, 64-row tile, 2 hedges per half-warp.
// smem: W fp32 64KB + Xs 32KB = 96KB -> 2 blocks/SM = 32 warps/SM.
// ---------------------------------------------------------------------------
__global__ void __launch_bounds__(512)
hedge_gemm_kernel(const __half* __restrict__ xh, const float* __restrict__ W,
                  __half* __restrict__ m2h) {
    extern __shared__ float sm[];
    float* Ws = sm;              // 128*128
    float* Xs = sm + 128 * 128;  // 64*128
    int t    = threadIdx.x;
    int lane = t & 31;
    int l16  = lane & 15;
    int base = lane & 16;        // 0 or 16
    unsigned mask = base ? 0xffff0000u : 0x0000ffffu;
    int hw   = t >> 4;           // half-warp id 0..31

    for (int i = t; i < 128 * 128 / 4; i += 512)
        ((float4*)Ws)[i] = ((const float4*)W)[i];

    int row0 = blockIdx.x * 64;

    // Phase A: gather. Half-warp hw handles hedge rows hw*2 + {0,1}.
    #pragma unroll
    for (int r = 0; r < 2; r++) {
        int hr = hw * 2 + r;           // 0..63
        int h  = row0 + hr;
        float2 a[4] = {{0.f,0.f},{0.f,0.f},{0.f,0.f},{0.f,0.f}};
        if (h < N_HEDGE) {
            int start = g_off_e[h];
            int deg   = g_dege[h];
            gather_rows16(xh, start, deg, mask, base, l16, g_adj_e, a);
            float s = deg > 0 ? 1.0f / (float)deg : 0.0f;
            #pragma unroll
            for (int q = 0; q < 4; q++) { a[q].x *= s; a[q].y *= s; }
        }
        // lane owns floats [8*l16 .. 8*l16+7] of the row
        float* xr = Xs + hr * 128 + l16 * 8;
        ((float4*)xr)[0] = make_float4(a[0].x, a[0].y, a[1].x, a[1].y);
        ((float4*)xr)[1] = make_float4(a[2].x, a[2].y, a[3].x, a[3].y);
    }
    __syncthreads();

    // Phase B: 64x128 @ 128x128 fp32 GEMM (f32x2 FMA).
    int tx = t & 31;   // col group: floats [4*tx .. 4*tx+3]
    int ty = t >> 5;   // 0..15; rows ty, ty+16, ty+32, ty+48
    unsigned long long acc01[4], acc23[4];
    #pragma unroll
    for (int r = 0; r < 4; r++) { acc01[r] = 0ull; acc23[r] = 0ull; }

    #pragma unroll 4
    for (int k = 0; k < 128; k++) {
        ulonglong2 wv = ((const ulonglong2*)(Ws + k * 128))[tx];
        #pragma unroll
        for (int r = 0; r < 4; r++) {
            float a = Xs[(ty + r * 16) * 128 + k];
            unsigned long long aa = pack2(a, a);
            fma2(acc01[r], aa, wv.x);
            fma2(acc23[r], aa, wv.y);
        }
    }

    #pragma unroll
    for (int r = 0; r < 4; r++) {
        int gr = row0 + ty + r * 16;
        if (gr < N_HEDGE) {
            float c0, c1, c2, c3;
            unpack2(acc01[r], c0, c1);
            unpack2(acc23[r], c2, c3);
            __half2 h0 = __floats2half2_rn(c0, c1);
            __half2 h1 = __floats2half2_rn(c2, c3);
            uint2 pv;
            pv.x = *(unsigned int*)&h0;
            pv.y = *(unsigned int*)&h1;
            ((uint2*)(m2h + (size_t)gr * D))[tx] = pv;
        }
    }
}

// ---------------------------------------------------------------------------
// Fused node stage: 2 nodes per warp (one per half-warp).
// ---------------------------------------------------------------------------
__device__ __forceinline__ float elu_f(float v) {
    return v > 0.0f ? v : expm1f(v);
}

template <bool LAST>
__global__ void __launch_bounds__(256)
node_gather_kernel(const __half* __restrict__ m2h, const float* __restrict__ bias,
                   float* __restrict__ out) {
    int lane = threadIdx.x & 31;
    int l16  = lane & 15;
    int base = lane & 16;
    unsigned mask = base ? 0xffff0000u : 0x0000ffffu;
    int gw   = ((blockIdx.x * blockDim.x + threadIdx.x) >> 4);  // node id
    if (gw >= N_NODES) return;

    int start = g_off_n[gw];
    int deg   = g_degn[gw];

    float2 a[4] = {{0.f,0.f},{0.f,0.f},{0.f,0.f},{0.f,0.f}};
    gather_rows16(m2h, start, deg, mask, base, l16, g_adj_n, a);

    float s = deg > 0 ? 1.0f / (float)deg : 0.0f;
    float4 b0 = ((const float4*)bias)[2 * l16];
    float4 b1 = ((const float4*)bias)[2 * l16 + 1];
    float v0 = elu_f(fmaf(a[0].x, s, b0.x));
    float v1 = elu_f(fmaf(a[0].y, s, b0.y));
    float v2 = elu_f(fmaf(a[1].x, s, b0.z));
    float v3 = elu_f(fmaf(a[1].y, s, b0.w));
    float v4 = elu_f(fmaf(a[2].x, s, b1.x));
    float v5 = elu_f(fmaf(a[2].y, s, b1.y));
    float v6 = elu_f(fmaf(a[3].x, s, b1.z));
    float v7 = elu_f(fmaf(a[3].y, s, b1.w));

    if (LAST) {
        float4* orow = (float4*)(out + (size_t)gw * D);
        orow[2 * l16]     = make_float4(v0, v1, v2, v3);
        orow[2 * l16 + 1] = make_float4(v4, v5, v6, v7);
    } else {
        __half2 h0 = __floats2half2_rn(v0, v1);
        __half2 h1 = __floats2half2_rn(v2, v3);
        __half2 h2 = __floats2half2_rn(v4, v5);
        __half2 h3 = __floats2half2_rn(v6, v7);
        uint4 pv;
        pv.x = *(unsigned int*)&h0;
        pv.y = *(unsigned int*)&h1;
        pv.z = *(unsigned int*)&h2;
        pv.w = *(unsigned int*)&h3;
        ((uint4*)(g_xh + (size_t)gw * D))[l16] = pv;
    }
}

// ---------------------------------------------------------------------------
// Launch
// ---------------------------------------------------------------------------
extern "C" void kernel_launch(void* const* d_in, const int* in_sizes, int n_in,
                              void* d_out, int out_size) {
    const float* x  = (const float*)d_in[0];
    const float* W1 = (const float*)d_in[1];
    const float* b1 = (const float*)d_in[2];
    const float* W2 = (const float*)d_in[3];
    const float* b2 = (const float*)d_in[4];
    const float* W3 = (const float*)d_in[5];
    const float* b3 = (const float*)d_in[6];
    const int* node_idx  = (const int*)d_in[7];
    const int* hedge_idx = (const int*)d_in[8];
    float* out = (float*)d_out;

    __half *p_xh, *p_m2h;
    cudaGetSymbolAddress((void**)&p_xh,  g_xh);
    cudaGetSymbolAddress((void**)&p_m2h, g_m2h);

    const int GEMM_SMEM = (128 * 128 + 64 * 128) * (int)sizeof(float);  // 96KB
    cudaFuncSetAttribute(hedge_gemm_kernel,
                         cudaFuncAttributeMaxDynamicSharedMemorySize, GEMM_SMEM);

    const int EB = (N_EDGES + 255) / 256;

    zero_deg_kernel<<<NB_N, 256>>>();
    count_deg_kernel<<<EB, 256>>>(node_idx, hedge_idx);
    scan_chunk_both_kernel<<<NB_N + NB_E, 256>>>();
    scan_bsum_both_kernel<<<2, 512>>>();
    scan_add_both_kernel<<<NB_N + NB_E, 256>>>();
    fill_adj_kernel<<<EB, 256>>>(node_idx, hedge_idx);

    convert_x_kernel<<<(N_NODES * D / 4 + 255) / 256, 256>>>(x);

    const int HGB = (N_HEDGE + 63) / 64;            // 391
    const int NGB = (N_NODES * 16 + 255) / 256;     // 6250

    hedge_gemm_kernel<<<HGB, 512, GEMM_SMEM>>>(p_xh, W1, p_m2h);
    node_gather_kernel<false><<<NGB, 256>>>(p_m2h, b1, nullptr);

    hedge_gemm_kernel<<<HGB, 512, GEMM_SMEM>>>(p_xh, W2, p_m2h);
    node_gather_kernel<false><<<NGB, 256>>>(p_m2h, b2, nullptr);

    hedge_gemm_kernel<<<HGB, 512, GEMM_SMEM>>>(p_xh, W3, p_m2h);
    node_gather_kernel<true><<<NGB, 256>>>(p_m2h, b3, out);
}

// round 8
// speedup vs baseline: 2.3825x; 1.0789x over previous
#include <cuda_runtime.h>
#include <cuda_fp16.h>
#include <math.h>

constexpr int N_NODES = 100000;
constexpr int N_HEDGE = 25000;
constexpr int N_EDGES = 600000;
constexpr int D       = 128;

constexpr int NB_N = (N_NODES + 255) / 256;   // 391
constexpr int NB_E = (N_HEDGE + 255) / 256;   // 98

// Padded adjacency capacities (each segment rounded up to multiple of 4)
constexpr int ADJ_E_CAP = N_EDGES + 3 * N_HEDGE;   // 675000
constexpr int ADJ_N_CAP = N_EDGES + 3 * N_NODES;   // 900000
constexpr int DUMMY_NODE  = N_NODES;   // zero row in g_xh
constexpr int DUMMY_HEDGE = N_HEDGE;   // zero row in g_m2h

// ---------------------------------------------------------------------------
// Scratch
// ---------------------------------------------------------------------------
__device__ __half g_xh [(N_NODES + 1) * D];   // +1 zero row
__device__ __half g_m2h[(N_HEDGE + 1) * D];   // +1 zero row
__device__ int   g_degn[N_NODES];
__device__ int   g_dege[N_HEDGE];
__device__ int   g_off_n[N_NODES];
__device__ int   g_off_e[N_HEDGE];
__device__ int   g_cur_n[N_NODES];
__device__ int   g_cur_e[N_HEDGE];
__device__ __align__(16) int g_adj_e[ADJ_E_CAP];
__device__ __align__(16) int g_adj_n[ADJ_N_CAP];
__device__ int   g_total[2];

// ---------------------------------------------------------------------------
// Packed f32x2 helpers
// ---------------------------------------------------------------------------
__device__ __forceinline__ void fma2(unsigned long long& d, unsigned long long a,
                                     unsigned long long b) {
    asm("fma.rn.f32x2 %0, %1, %2, %0;" : "+l"(d) : "l"(a), "l"(b));
}
__device__ __forceinline__ unsigned long long pack2(float lo, float hi) {
    unsigned long long d;
    asm("mov.b64 %0, {%1, %2};" : "=l"(d) : "f"(lo), "f"(hi));
    return d;
}
__device__ __forceinline__ void unpack2(unsigned long long v, float& lo, float& hi) {
    asm("mov.b64 {%0, %1}, %2;" : "=f"(lo), "=f"(hi) : "l"(v));
}

// ---------------------------------------------------------------------------
// Preproc: single init kernel (degs, dummy adj fill, zero rows, totals)
// ---------------------------------------------------------------------------
__global__ void init_kernel() {
    int i = blockIdx.x * blockDim.x + threadIdx.x;
    if (i < N_NODES) g_degn[i] = 0;
    if (i < N_HEDGE) g_dege[i] = 0;
    if (i < ADJ_N_CAP) g_adj_n[i] = DUMMY_HEDGE;
    if (i < ADJ_E_CAP) g_adj_e[i] = DUMMY_NODE;
    if (i < D) {
        g_xh [(size_t)N_NODES * D + i] = __float2half(0.f);
        g_m2h[(size_t)N_HEDGE * D + i] = __float2half(0.f);
    }
    if (i < 2) g_total[i] = 0;
}

__global__ void count_deg_kernel(const int* __restrict__ node_idx,
                                 const int* __restrict__ hedge_idx) {
    int i = blockIdx.x * blockDim.x + threadIdx.x;
    if (i < N_EDGES) {
        atomicAdd(&g_degn[node_idx[i]], 1);
        atomicAdd(&g_dege[hedge_idx[i]], 1);
    }
}

// ---------------------------------------------------------------------------
// One-kernel scan: per-chunk exclusive prefix of PADDED degrees; chunk base
// from atomicAdd on g_total (placement nondeterministic, output invariant).
// ---------------------------------------------------------------------------
__global__ void scan_atomic_kernel() {
    __shared__ int s[256];
    __shared__ int sbase;
    bool is_n = blockIdx.x < NB_N;
    int blk   = is_n ? blockIdx.x : blockIdx.x - NB_N;
    const int* cnt = is_n ? g_degn : g_dege;
    int*       off = is_n ? g_off_n : g_off_e;
    int*       cur = is_n ? g_cur_n : g_cur_e;
    int n          = is_n ? N_NODES : N_HEDGE;

    int i = blk * 256 + threadIdx.x;
    int v = (i < n) ? ((cnt[i] + 3) & ~3) : 0;   // padded degree
    s[threadIdx.x] = v;
    __syncthreads();
    #pragma unroll
    for (int d = 1; d < 256; d <<= 1) {
        int t = (threadIdx.x >= d) ? s[threadIdx.x - d] : 0;
        __syncthreads();
        s[threadIdx.x] += t;
        __syncthreads();
    }
    if (threadIdx.x == 255)
        sbase = atomicAdd(&g_total[is_n ? 0 : 1], s[255]);
    __syncthreads();
    if (i < n) {
        int o = sbase + s[threadIdx.x] - v;
        off[i] = o;
        cur[i] = o;
    }
}

__global__ void fill_adj_kernel(const int* __restrict__ node_idx,
                                const int* __restrict__ hedge_idx) {
    int e = blockIdx.x * blockDim.x + threadIdx.x;
    if (e >= N_EDGES) return;
    int nd = node_idx[e];
    int h  = hedge_idx[e];
    g_adj_e[atomicAdd(&g_cur_e[h],  1)] = nd;
    g_adj_n[atomicAdd(&g_cur_n[nd], 1)] = h;
}

__global__ void convert_x_kernel(const float* __restrict__ x) {
    int i = blockIdx.x * blockDim.x + threadIdx.x;
    if (i >= N_NODES * D / 4) return;
    float4 v = ((const float4*)x)[i];
    __half2 h0 = __floats2half2_rn(v.x, v.y);
    __half2 h1 = __floats2half2_rn(v.z, v.w);
    ((__half2*)g_xh)[i * 2]     = h0;
    ((__half2*)g_xh)[i * 2 + 1] = h1;
}

// ---------------------------------------------------------------------------
// Shuffle-free half-warp gather. Segments padded to multiple of 4 with dummy
// (zero-row) indices; indices read as uniform int4 (L1 broadcast).
// Batch-8: 8 independent row loads in flight.
// ---------------------------------------------------------------------------
__device__ __forceinline__ void acc_row16(uint4 v, float2* a) {
    float2 f0 = __half22float2(*(const __half2*)&v.x);
    float2 f1 = __half22float2(*(const __half2*)&v.y);
    float2 f2 = __half22float2(*(const __half2*)&v.z);
    float2 f3 = __half22float2(*(const __half2*)&v.w);
    a[0].x += f0.x; a[0].y += f0.y;
    a[1].x += f1.x; a[1].y += f1.y;
    a[2].x += f2.x; a[2].y += f2.y;
    a[3].x += f3.x; a[3].y += f3.y;
}

__device__ __forceinline__ void gather16(const __half* __restrict__ src,
                                         const int* __restrict__ adj,
                                         int start, int deg, int l16,
                                         float2* a) {
    int deg4 = (deg + 3) & ~3;
    int j = 0;
    for (; j + 8 <= deg4; j += 8) {
        int4 iv0 = *(const int4*)(adj + start + j);
        int4 iv1 = *(const int4*)(adj + start + j + 4);
        uint4 r0 = ((const uint4*)(src + (size_t)iv0.x * D))[l16];
        uint4 r1 = ((const uint4*)(src + (size_t)iv0.y * D))[l16];
        uint4 r2 = ((const uint4*)(src + (size_t)iv0.z * D))[l16];
        uint4 r3 = ((const uint4*)(src + (size_t)iv0.w * D))[l16];
        uint4 r4 = ((const uint4*)(src + (size_t)iv1.x * D))[l16];
        uint4 r5 = ((const uint4*)(src + (size_t)iv1.y * D))[l16];
        uint4 r6 = ((const uint4*)(src + (size_t)iv1.z * D))[l16];
        uint4 r7 = ((const uint4*)(src + (size_t)iv1.w * D))[l16];
        acc_row16(r0, a); acc_row16(r1, a); acc_row16(r2, a); acc_row16(r3, a);
        acc_row16(r4, a); acc_row16(r5, a); acc_row16(r6, a); acc_row16(r7, a);
    }
    if (j < deg4) {   // one remaining batch of 4
        int4 iv = *(const int4*)(adj + start + j);
        uint4 r0 = ((const uint4*)(src + (size_t)iv.x * D))[l16];
        uint4 r1 = ((const uint4*)(src + (size_t)iv.y * D))[l16];
        uint4 r2 = ((const uint4*)(src + (size_t)iv.z * D))[l16];
        uint4 r3 = ((const uint4*)(src + (size_t)iv.w * D))[l16];
        acc_row16(r0, a); acc_row16(r1, a); acc_row16(r2, a); acc_row16(r3, a);
    }
}

// ---------------------------------------------------------------------------
// Fused hyperedge stage: 512 threads, 64-row tile, 2 hedges per half-warp.
// ---------------------------------------------------------------------------
__global__ void __launch_bounds__(512)
hedge_gemm_kernel(const __half* __restrict__ xh, const float* __restrict__ W,
                  __half* __restrict__ m2h) {
    extern __shared__ float sm[];
    float* Ws = sm;              // 128*128
    float* Xs = sm + 128 * 128;  // 64*128
    int t    = threadIdx.x;
    int lane = t & 31;
    int l16  = lane & 15;
    int hw   = t >> 4;           // half-warp id 0..31

    for (int i = t; i < 128 * 128 / 4; i += 512)
        ((float4*)Ws)[i] = ((const float4*)W)[i];

    int row0 = blockIdx.x * 64;

    #pragma unroll
    for (int r = 0; r < 2; r++) {
        int hr = hw * 2 + r;
        int h  = row0 + hr;
        float2 a[4] = {{0.f,0.f},{0.f,0.f},{0.f,0.f},{0.f,0.f}};
        if (h < N_HEDGE) {
            int start = g_off_e[h];
            int deg   = g_dege[h];
            gather16(xh, g_adj_e, start, deg, l16, a);
            float s = deg > 0 ? 1.0f / (float)deg : 0.0f;
            #pragma unroll
            for (int q = 0; q < 4; q++) { a[q].x *= s; a[q].y *= s; }
        }
        float* xr = Xs + hr * 128 + l16 * 8;
        ((float4*)xr)[0] = make_float4(a[0].x, a[0].y, a[1].x, a[1].y);
        ((float4*)xr)[1] = make_float4(a[2].x, a[2].y, a[3].x, a[3].y);
    }
    __syncthreads();

    // 64x128 @ 128x128 fp32 GEMM (f32x2 FMA)
    int tx = t & 31;
    int ty = t >> 5;
    unsigned long long acc01[4], acc23[4];
    #pragma unroll
    for (int r = 0; r < 4; r++) { acc01[r] = 0ull; acc23[r] = 0ull; }

    #pragma unroll 4
    for (int k = 0; k < 128; k++) {
        ulonglong2 wv = ((const ulonglong2*)(Ws + k * 128))[tx];
        #pragma unroll
        for (int r = 0; r < 4; r++) {
            float a = Xs[(ty + r * 16) * 128 + k];
            unsigned long long aa = pack2(a, a);
            fma2(acc01[r], aa, wv.x);
            fma2(acc23[r], aa, wv.y);
        }
    }

    #pragma unroll
    for (int r = 0; r < 4; r++) {
        int gr = row0 + ty + r * 16;
        if (gr < N_HEDGE) {
            float c0, c1, c2, c3;
            unpack2(acc01[r], c0, c1);
            unpack2(acc23[r], c2, c3);
            __half2 h0 = __floats2half2_rn(c0, c1);
            __half2 h1 = __floats2half2_rn(c2, c3);
            uint2 pv;
            pv.x = *(unsigned int*)&h0;
            pv.y = *(unsigned int*)&h1;
            ((uint2*)(m2h + (size_t)gr * D))[tx] = pv;
        }
    }
}

// ---------------------------------------------------------------------------
// Fused node stage: 1 node per half-warp.
// ---------------------------------------------------------------------------
__device__ __forceinline__ float elu_f(float v) {
    return v > 0.0f ? v : expm1f(v);
}

template <bool LAST>
__global__ void __launch_bounds__(256)
node_gather_kernel(const __half* __restrict__ m2h, const float* __restrict__ bias,
                   float* __restrict__ out) {
    int lane = threadIdx.x & 31;
    int l16  = lane & 15;
    int gw   = ((blockIdx.x * blockDim.x + threadIdx.x) >> 4);  // node id
    if (gw >= N_NODES) return;

    int start = g_off_n[gw];
    int deg   = g_degn[gw];

    float2 a[4] = {{0.f,0.f},{0.f,0.f},{0.f,0.f},{0.f,0.f}};
    gather16(m2h, g_adj_n, start, deg, l16, a);

    float s = deg > 0 ? 1.0f / (float)deg : 0.0f;
    float4 b0 = ((const float4*)bias)[2 * l16];
    float4 b1 = ((const float4*)bias)[2 * l16 + 1];
    float v0 = elu_f(fmaf(a[0].x, s, b0.x));
    float v1 = elu_f(fmaf(a[0].y, s, b0.y));
    float v2 = elu_f(fmaf(a[1].x, s, b0.z));
    float v3 = elu_f(fmaf(a[1].y, s, b0.w));
    float v4 = elu_f(fmaf(a[2].x, s, b1.x));
    float v5 = elu_f(fmaf(a[2].y, s, b1.y));
    float v6 = elu_f(fmaf(a[3].x, s, b1.z));
    float v7 = elu_f(fmaf(a[3].y, s, b1.w));

    if (LAST) {
        float4* orow = (float4*)(out + (size_t)gw * D);
        orow[2 * l16]     = make_float4(v0, v1, v2, v3);
        orow[2 * l16 + 1] = make_float4(v4, v5, v6, v7);
    } else {
        __half2 h0 = __floats2half2_rn(v0, v1);
        __half2 h1 = __floats2half2_rn(v2, v3);
        __half2 h2 = __floats2half2_rn(v4, v5);
        __half2 h3 = __floats2half2_rn(v6, v7);
        uint4 pv;
        pv.x = *(unsigned int*)&h0;
        pv.y = *(unsigned int*)&h1;
        pv.z = *(unsigned int*)&h2;
        pv.w = *(unsigned int*)&h3;
        ((uint4*)(g_xh + (size_t)gw * D))[l16] = pv;
    }
}

// ---------------------------------------------------------------------------
// Launch
// ---------------------------------------------------------------------------
extern "C" void kernel_launch(void* const* d_in, const int* in_sizes, int n_in,
                              void* d_out, int out_size) {
    const float* x  = (const float*)d_in[0];
    const float* W1 = (const float*)d_in[1];
    const float* b1 = (const float*)d_in[2];
    const float* W2 = (const float*)d_in[3];
    const float* b2 = (const float*)d_in[4];
    const float* W3 = (const float*)d_in[5];
    const float* b3 = (const float*)d_in[6];
    const int* node_idx  = (const int*)d_in[7];
    const int* hedge_idx = (const int*)d_in[8];
    float* out = (float*)d_out;

    __half *p_xh, *p_m2h;
    cudaGetSymbolAddress((void**)&p_xh,  g_xh);
    cudaGetSymbolAddress((void**)&p_m2h, g_m2h);

    const int GEMM_SMEM = (128 * 128 + 64 * 128) * (int)sizeof(float);  // 96KB
    cudaFuncSetAttribute(hedge_gemm_kernel,
                         cudaFuncAttributeMaxDynamicSharedMemorySize, GEMM_SMEM);

    const int EB = (N_EDGES + 255) / 256;

    // Preproc: 5 launches
    init_kernel<<<(ADJ_N_CAP + 255) / 256, 256>>>();
    count_deg_kernel<<<EB, 256>>>(node_idx, hedge_idx);
    scan_atomic_kernel<<<NB_N + NB_E, 256>>>();
    fill_adj_kernel<<<EB, 256>>>(node_idx, hedge_idx);
    convert_x_kernel<<<(N_NODES * D / 4 + 255) / 256, 256>>>(x);

    const int HGB = (N_HEDGE + 63) / 64;            // 391
    const int NGB = (N_NODES * 16 + 255) / 256;     // 6250

    hedge_gemm_kernel<<<HGB, 512, GEMM_SMEM>>>(p_xh, W1, p_m2h);
    node_gather_kernel<false><<<NGB, 256>>>(p_m2h, b1, nullptr);

    hedge_gemm_kernel<<<HGB, 512, GEMM_SMEM>>>(p_xh, W2, p_m2h);
    node_gather_kernel<false><<<NGB, 256>>>(p_m2h, b2, nullptr);

    hedge_gemm_kernel<<<HGB, 512, GEMM_SMEM>>>(p_xh, W3, p_m2h);
    node_gather_kernel<true><<<NGB, 256>>>(p_m2h, b3, out);
}